// round 7
// baseline (speedup 1.0000x reference)
#include <cuda_runtime.h>
#include <cstdint>

// SecureSwishFeedForward via legacy TF32 mma.sync (m16n8k8).
// (Harness PTX stage targets compute_103 — no tcgen05.)
//
// out = swish_poly(X @ W1^T + b1) @ W2^T + b2
// X:[8192,1024] W1:[4096,1024] W2:[1024,4096], fp32 row-major, K contiguous.
//
// R7: fragment loads via ldmatrix.m8n8.x4 (6 LDSM per warp per k8 step instead
// of 24 LDS.32) + register double-buffering of the k8 fragments so LDSM latency
// hides behind the 16 HMMAs of the previous step.

#define BM 128
#define BN 128
#define BK 32
#define PAD 4
#define LDSS (BK + PAD)                      // 36 floats
#define A_STAGE_F (BM * LDSS)                // floats per A stage (4608)
#define STAGE_F   (2 * A_STAGE_F)            // floats per stage (9216)
#define STAGE_BYTES (STAGE_F * 4)            // 36864
#define STAGES 3
#define NTHREADS 256
#define SMEM_DYN (STAGES * STAGE_BYTES)      // 110592 bytes

__device__ float g_mid[8192UL * 4096UL];
__device__ float g_Xr [8192UL * 1024UL];
__device__ float g_W1r[4096UL * 1024UL];
__device__ float g_W2r[1024UL * 4096UL];

__device__ __forceinline__ uint32_t stou(const void* p) {
    uint32_t a;
    asm("{ .reg .u64 t; cvta.to.shared.u64 t, %1; cvt.u32.u64 %0, t; }"
        : "=r"(a) : "l"(p));
    return a;
}

__device__ __forceinline__ void cpa16(const float* smem_dst, const float* gsrc) {
    uint32_t a = stou(smem_dst);
    asm volatile("cp.async.cg.shared.global [%0], [%1], 16;" :: "r"(a), "l"(gsrc));
}

// ldmatrix x4: four 8x(16B) row-matrices; lane t supplies the row address for
// matrix t/8. For 32-bit elements each thread receives element (lane/4, lane%4)
// of each matrix — exactly the tf32 m16n8k8 fragment layout.
#define LDSM4(r, addr) \
    asm volatile("ldmatrix.sync.aligned.m8n8.x4.shared.b16 {%0,%1,%2,%3}, [%4];" \
                 : "=r"((r)[0]), "=r"((r)[1]), "=r"((r)[2]), "=r"((r)[3])       \
                 : "r"(addr))

template<bool SWISH, bool ROUND_OUT>
__global__ __launch_bounds__(NTHREADS, 2)
void ffn_gemm(const float* __restrict__ A,    // [M, K] tf32-rounded
              const float* __restrict__ B,    // [N, K] tf32-rounded
              const float* __restrict__ bias, // [N]
              float* __restrict__ C,          // [M, N]
              int M, int N, int K)
{
    extern __shared__ __align__(16) float smem[];
    const uint32_t smem_u32 = stou(smem);

    const int tid  = threadIdx.x;
    const int wid  = tid >> 5, lane = tid & 31;
    const int wr   = wid >> 2, wc   = wid & 3;   // 2x4 warp grid -> 64x32 warp tile
    const int lr   = lane >> 2, lc  = lane & 3;
    const int rowBase = blockIdx.y * BM;
    const int colBase = blockIdx.x * BN;
    const int NC = K / BK;

    // Per-lane ldmatrix byte offsets within a stage.
    // A frag mi (16x8): matrices {rows 0-7,k0-3},{rows 8-15,k0-3},{rows 0-7,k4-7},{rows 8-15,k4-7}
    //   lane t: row += (t>>3 & 1)*8, k += (t>>4 & 1)*4
    // B pair p (covers ni=2p,2p+1): matrices {n 0-7,k0-3},{n 0-7,k4-7},{n 8-15,k0-3},{n 8-15,k4-7}
    //   lane t: n += (t>>4 & 1)*8, k += (t>>3 & 1)*4
    const int t8  = lane & 7;
    const int tb3 = (lane >> 3) & 1;
    const int tb4 = (lane >> 4) & 1;
    uint32_t a_off[4], b_off[2];
#pragma unroll
    for (int mi = 0; mi < 4; mi++)
        a_off[mi] = (uint32_t)(((wr * 64 + mi * 16 + t8 + tb3 * 8) * LDSS + tb4 * 4) * 4);
#pragma unroll
    for (int p = 0; p < 2; p++)
        b_off[p] = (uint32_t)((A_STAGE_F + (wc * 32 + p * 16 + t8 + tb4 * 8) * LDSS + tb3 * 4) * 4);

    float acc[4][4][4];
#pragma unroll
    for (int mi = 0; mi < 4; mi++)
#pragma unroll
        for (int ni = 0; ni < 4; ni++)
#pragma unroll
            for (int e = 0; e < 4; e++) acc[mi][ni][e] = 0.0f;

    // Stage load: A tile 128 rows x 8 float4, B tile same; 8 cp.async/thread.
    const int ldrow = tid >> 3;
    const int ldq   = (tid & 7) * 4;
    #define LOAD_STAGE(s, c) do {                                              \
        float* sa_ = smem + (s) * STAGE_F;                                     \
        float* sb_ = sa_ + A_STAGE_F;                                          \
        _Pragma("unroll")                                                      \
        for (int it_ = 0; it_ < 4; it_++) {                                    \
            int row_ = ldrow + it_ * 32;                                       \
            cpa16(sa_ + row_ * LDSS + ldq,                                     \
                  A + (size_t)(rowBase + row_) * K + (c) * BK + ldq);          \
        }                                                                      \
        _Pragma("unroll")                                                      \
        for (int it_ = 0; it_ < 4; it_++) {                                    \
            int row_ = ldrow + it_ * 32;                                       \
            cpa16(sb_ + row_ * LDSS + ldq,                                     \
                  B + (size_t)(colBase + row_) * K + (c) * BK + ldq);          \
        }                                                                      \
    } while (0)

    // Fragment load for one k8 step into a register buffer set.
    #define LOADK(k8, afb, bfb) do {                                           \
        _Pragma("unroll")                                                      \
        for (int mi_ = 0; mi_ < 4; mi_++)                                      \
            LDSM4((afb)[mi_], sbase + a_off[mi_] + (k8) * 32);                 \
        _Pragma("unroll")                                                      \
        for (int p_ = 0; p_ < 2; p_++)                                         \
            LDSM4((bfb)[p_], sbase + b_off[p_] + (k8) * 32);                   \
    } while (0)

    #define DO_MMAS(afb, bfb) do {                                             \
        _Pragma("unroll")                                                      \
        for (int mi_ = 0; mi_ < 4; mi_++)                                      \
            _Pragma("unroll")                                                  \
            for (int ni_ = 0; ni_ < 4; ni_++)                                  \
                asm volatile(                                                  \
                    "mma.sync.aligned.m16n8k8.row.col.f32.tf32.tf32.f32 "      \
                    "{%0,%1,%2,%3}, {%4,%5,%6,%7}, {%8,%9}, {%0,%1,%2,%3};"    \
                    : "+f"(acc[mi_][ni_][0]), "+f"(acc[mi_][ni_][1]),          \
                      "+f"(acc[mi_][ni_][2]), "+f"(acc[mi_][ni_][3])           \
                    : "r"((afb)[mi_][0]), "r"((afb)[mi_][1]),                  \
                      "r"((afb)[mi_][2]), "r"((afb)[mi_][3]),                  \
                      "r"((bfb)[ni_ >> 1][(ni_ & 1) * 2]),                     \
                      "r"((bfb)[ni_ >> 1][(ni_ & 1) * 2 + 1]));                \
    } while (0)

    // Prologue: fill STAGES-1 stages.
#pragma unroll
    for (int s = 0; s < STAGES - 1; s++) {
        if (s < NC) LOAD_STAGE(s, s);
        asm volatile("cp.async.commit_group;" ::: "memory");
    }

    for (int c = 0; c < NC; c++) {
        if (c + STAGES - 1 < NC) {
            int s = (c + STAGES - 1) % STAGES;
            LOAD_STAGE(s, c + STAGES - 1);
        }
        asm volatile("cp.async.commit_group;" ::: "memory");
        asm volatile("cp.async.wait_group %0;" :: "n"(STAGES - 1) : "memory");
        __syncthreads();

        const uint32_t sbase = smem_u32 + (c % STAGES) * STAGE_BYTES;

        uint32_t af[2][4][4], bf[2][2][4];
        LOADK(0, af[0], bf[0]);
#pragma unroll
        for (int k8 = 0; k8 < 4; k8++) {
            const int cur = k8 & 1;
            if (k8 < 3) LOADK(k8 + 1, af[cur ^ 1], bf[cur ^ 1]);
            DO_MMAS(af[cur], bf[cur]);
        }
        __syncthreads();
    }

    // Epilogue: bias + optional poly-swish (+ optional tf32 re-round).
#pragma unroll
    for (int ni = 0; ni < 4; ni++) {
        const int col = colBase + wc * 32 + ni * 8 + 2 * lc;
        const float bv0 = __ldg(bias + col);
        const float bv1 = __ldg(bias + col + 1);
#pragma unroll
        for (int mi = 0; mi < 4; mi++) {
#pragma unroll
            for (int h = 0; h < 2; h++) {
                const int row = rowBase + wr * 64 + mi * 16 + lr + h * 8;
                float v0 = acc[mi][ni][2 * h]     + bv0;
                float v1 = acc[mi][ni][2 * h + 1] + bv1;
                if (SWISH) {
                    float s0 = fmaf(-0.0208f * v0 * v0, v0, fmaf(0.25f, v0, 0.5f));
                    float s1 = fmaf(-0.0208f * v1 * v1, v1, fmaf(0.25f, v1, 0.5f));
                    v0 *= s0; v1 *= s1;
                }
                if (ROUND_OUT) {
                    asm("cvt.rn.tf32.f32 %0, %0;" : "+f"(v0));
                    asm("cvt.rn.tf32.f32 %0, %0;" : "+f"(v1));
                }
                *reinterpret_cast<float2*>(C + (size_t)row * N + col) =
                    make_float2(v0, v1);
            }
        }
    }
}

// ------------------------- tf32 rounding pre-pass ---------------------------

__global__ void round_tf32_kernel(const float4* __restrict__ in,
                                  float4* __restrict__ out, int n4)
{
    int i = blockIdx.x * blockDim.x + threadIdx.x;
    if (i < n4) {
        float4 v = in[i];
        asm("cvt.rn.tf32.f32 %0, %0;" : "+f"(v.x));
        asm("cvt.rn.tf32.f32 %0, %0;" : "+f"(v.y));
        asm("cvt.rn.tf32.f32 %0, %0;" : "+f"(v.z));
        asm("cvt.rn.tf32.f32 %0, %0;" : "+f"(v.w));
        out[i] = v;
    }
}

// ------------------------------- launch -------------------------------------

extern "C" void kernel_launch(void* const* d_in, const int* in_sizes, int n_in,
                              void* d_out, int out_size)
{
    const float* X  = (const float*)d_in[0]; // [M, D]
    const float* W1 = (const float*)d_in[1]; // [F, D]
    const float* b1 = (const float*)d_in[2]; // [F]
    const float* W2 = (const float*)d_in[3]; // [D, F]
    const float* b2 = (const float*)d_in[4]; // [D]
    float* out = (float*)d_out;              // [M, D]

    const int F = in_sizes[2];               // 4096
    const int D = in_sizes[4];               // 1024
    const int M = in_sizes[0] / D;           // 8192

    float *mid, *Xr, *W1r, *W2r;
    cudaGetSymbolAddress((void**)&mid, g_mid);
    cudaGetSymbolAddress((void**)&Xr,  g_Xr);
    cudaGetSymbolAddress((void**)&W1r, g_W1r);
    cudaGetSymbolAddress((void**)&W2r, g_W2r);

    cudaFuncSetAttribute(ffn_gemm<true,  true >,
                         cudaFuncAttributeMaxDynamicSharedMemorySize, SMEM_DYN);
    cudaFuncSetAttribute(ffn_gemm<false, false>,
                         cudaFuncAttributeMaxDynamicSharedMemorySize, SMEM_DYN);

    // Round inputs to tf32 (RN) so MMA truncation is zero-mean.
    int n4;
    n4 = (M * D) / 4;
    round_tf32_kernel<<<(n4 + 255) / 256, 256>>>((const float4*)X,  (float4*)Xr,  n4);
    n4 = (F * D) / 4;
    round_tf32_kernel<<<(n4 + 255) / 256, 256>>>((const float4*)W1, (float4*)W1r, n4);
    n4 = (D * F) / 4;
    round_tf32_kernel<<<(n4 + 255) / 256, 256>>>((const float4*)W2, (float4*)W2r, n4);

    // GEMM1: mid = round_tf32(swish(X @ W1^T + b1))   [M, F], K = D
    {
        dim3 grid(F / BN, M / BM);
        ffn_gemm<true, true><<<grid, NTHREADS, SMEM_DYN>>>(Xr, W1r, b1, mid, M, F, D);
    }
    // GEMM2: out = mid @ W2^T + b2                    [M, D], K = F
    {
        dim3 grid(D / BN, M / BM);
        ffn_gemm<false, false><<<grid, NTHREADS, SMEM_DYN>>>(mid, W2r, b2, out, M, D, F);
    }
}

// round 8
// speedup vs baseline: 1.1440x; 1.1440x over previous
#include <cuda_runtime.h>
#include <cstdint>

// SecureSwishFeedForward via legacy TF32 mma.sync (m16n8k8).
// (Harness PTX stage targets compute_103 — no tcgen05.)
//
// out = swish_poly(X @ W1^T + b1) @ W2^T + b2
// X:[8192,1024] W1:[4096,1024] W2:[1024,4096], fp32 row-major, K contiguous.
//
// R8: SINGLE __syncthreads per mainloop iteration. Order per iter c:
//   cp.async.wait_group 1  (stage c's group is >=2 commits old -> complete)
//   __syncthreads          (all warps done reading stage (c-1)%3)
//   issue cp.async for stage c+2 (buffer (c+2)%3 == (c-1)%3, now free)
//   commit (unconditionally, keeps group ordering for wait_group 1)
//   LDSM + HMMA over stage c with k8 register double-buffer.

#define BM 128
#define BN 128
#define BK 32
#define PAD 4
#define LDSS (BK + PAD)                      // 36 floats
#define A_STAGE_F (BM * LDSS)                // floats per A stage (4608)
#define STAGE_F   (2 * A_STAGE_F)            // floats per stage (9216)
#define STAGE_BYTES (STAGE_F * 4)            // 36864
#define STAGES 3
#define NTHREADS 256
#define SMEM_DYN (STAGES * STAGE_BYTES)      // 110592 bytes

__device__ float g_mid[8192UL * 4096UL];
__device__ float g_Xr [8192UL * 1024UL];
__device__ float g_W1r[4096UL * 1024UL];
__device__ float g_W2r[1024UL * 4096UL];

__device__ __forceinline__ uint32_t stou(const void* p) {
    uint32_t a;
    asm("{ .reg .u64 t; cvta.to.shared.u64 t, %1; cvt.u32.u64 %0, t; }"
        : "=r"(a) : "l"(p));
    return a;
}

__device__ __forceinline__ void cpa16(const float* smem_dst, const float* gsrc) {
    uint32_t a = stou(smem_dst);
    asm volatile("cp.async.cg.shared.global [%0], [%1], 16;" :: "r"(a), "l"(gsrc));
}

// ldmatrix x4 (b16 path, 32-bit payload): lane gets element (lane/4, lane%4)
// of each 8x4-float matrix — the tf32 m16n8k8 fragment layout.
#define LDSM4(r, addr) \
    asm volatile("ldmatrix.sync.aligned.m8n8.x4.shared.b16 {%0,%1,%2,%3}, [%4];" \
                 : "=r"((r)[0]), "=r"((r)[1]), "=r"((r)[2]), "=r"((r)[3])       \
                 : "r"(addr))

template<bool SWISH, bool ROUND_OUT>
__global__ __launch_bounds__(NTHREADS, 2)
void ffn_gemm(const float* __restrict__ A,    // [M, K] tf32-rounded
              const float* __restrict__ B,    // [N, K] tf32-rounded
              const float* __restrict__ bias, // [N]
              float* __restrict__ C,          // [M, N]
              int M, int N, int K)
{
    extern __shared__ __align__(16) float smem[];
    const uint32_t smem_u32 = stou(smem);

    const int tid  = threadIdx.x;
    const int wid  = tid >> 5, lane = tid & 31;
    const int wr   = wid >> 2, wc   = wid & 3;   // 2x4 warp grid -> 64x32 warp tile
    const int lr   = lane >> 2, lc  = lane & 3;
    const int rowBase = blockIdx.y * BM;
    const int colBase = blockIdx.x * BN;
    const int NC = K / BK;

    const int t8  = lane & 7;
    const int tb3 = (lane >> 3) & 1;
    const int tb4 = (lane >> 4) & 1;
    uint32_t a_off[4], b_off[2];
#pragma unroll
    for (int mi = 0; mi < 4; mi++)
        a_off[mi] = (uint32_t)(((wr * 64 + mi * 16 + t8 + tb3 * 8) * LDSS + tb4 * 4) * 4);
#pragma unroll
    for (int p = 0; p < 2; p++)
        b_off[p] = (uint32_t)((A_STAGE_F + (wc * 32 + p * 16 + t8 + tb4 * 8) * LDSS + tb3 * 4) * 4);

    float acc[4][4][4];
#pragma unroll
    for (int mi = 0; mi < 4; mi++)
#pragma unroll
        for (int ni = 0; ni < 4; ni++)
#pragma unroll
            for (int e = 0; e < 4; e++) acc[mi][ni][e] = 0.0f;

    const int ldrow = tid >> 3;
    const int ldq   = (tid & 7) * 4;
    #define LOAD_STAGE(s, c) do {                                              \
        float* sa_ = smem + (s) * STAGE_F;                                     \
        float* sb_ = sa_ + A_STAGE_F;                                          \
        _Pragma("unroll")                                                      \
        for (int it_ = 0; it_ < 4; it_++) {                                    \
            int row_ = ldrow + it_ * 32;                                       \
            cpa16(sa_ + row_ * LDSS + ldq,                                     \
                  A + (size_t)(rowBase + row_) * K + (c) * BK + ldq);          \
        }                                                                      \
        _Pragma("unroll")                                                      \
        for (int it_ = 0; it_ < 4; it_++) {                                    \
            int row_ = ldrow + it_ * 32;                                       \
            cpa16(sb_ + row_ * LDSS + ldq,                                     \
                  B + (size_t)(colBase + row_) * K + (c) * BK + ldq);          \
        }                                                                      \
    } while (0)

    #define LOADK(k8, afb, bfb) do {                                           \
        _Pragma("unroll")                                                      \
        for (int mi_ = 0; mi_ < 4; mi_++)                                      \
            LDSM4((afb)[mi_], sbase + a_off[mi_] + (k8) * 32);                 \
        _Pragma("unroll")                                                      \
        for (int p_ = 0; p_ < 2; p_++)                                         \
            LDSM4((bfb)[p_], sbase + b_off[p_] + (k8) * 32);                   \
    } while (0)

    #define DO_MMAS(afb, bfb) do {                                             \
        _Pragma("unroll")                                                      \
        for (int mi_ = 0; mi_ < 4; mi_++)                                      \
            _Pragma("unroll")                                                  \
            for (int ni_ = 0; ni_ < 4; ni_++)                                  \
                asm volatile(                                                  \
                    "mma.sync.aligned.m16n8k8.row.col.f32.tf32.tf32.f32 "      \
                    "{%0,%1,%2,%3}, {%4,%5,%6,%7}, {%8,%9}, {%0,%1,%2,%3};"    \
                    : "+f"(acc[mi_][ni_][0]), "+f"(acc[mi_][ni_][1]),          \
                      "+f"(acc[mi_][ni_][2]), "+f"(acc[mi_][ni_][3])           \
                    : "r"((afb)[mi_][0]), "r"((afb)[mi_][1]),                  \
                      "r"((afb)[mi_][2]), "r"((afb)[mi_][3]),                  \
                      "r"((bfb)[ni_ >> 1][(ni_ & 1) * 2]),                     \
                      "r"((bfb)[ni_ >> 1][(ni_ & 1) * 2 + 1]));                \
    } while (0)

    // Prologue: fill stages 0 and 1.
#pragma unroll
    for (int s = 0; s < STAGES - 1; s++) {
        if (s < NC) LOAD_STAGE(s, s);
        asm volatile("cp.async.commit_group;" ::: "memory");
    }

    for (int c = 0; c < NC; c++) {
        // Stage c's group is >=2 commits old; <=1 outstanding => it's complete.
        asm volatile("cp.async.wait_group 1;" ::: "memory");
        __syncthreads();

        const uint32_t sbase = smem_u32 + (c % STAGES) * STAGE_BYTES;

        // Prefetch first k8 fragments, then issue next stage's gmem loads so
        // they overlap the whole MMA section.
        uint32_t af[2][4][4], bf[2][2][4];
        LOADK(0, af[0], bf[0]);

        if (c + STAGES - 1 < NC) {
            int s = (c + STAGES - 1) % STAGES;
            LOAD_STAGE(s, c + STAGES - 1);
        }
        asm volatile("cp.async.commit_group;" ::: "memory");

#pragma unroll
        for (int k8 = 0; k8 < 4; k8++) {
            const int cur = k8 & 1;
            if (k8 < 3) LOADK(k8 + 1, af[cur ^ 1], bf[cur ^ 1]);
            DO_MMAS(af[cur], bf[cur]);
        }
    }

    // Epilogue: bias + optional poly-swish (+ optional tf32 re-round).
#pragma unroll
    for (int ni = 0; ni < 4; ni++) {
        const int col = colBase + wc * 32 + ni * 8 + 2 * lc;
        const float bv0 = __ldg(bias + col);
        const float bv1 = __ldg(bias + col + 1);
#pragma unroll
        for (int mi = 0; mi < 4; mi++) {
#pragma unroll
            for (int h = 0; h < 2; h++) {
                const int row = rowBase + wr * 64 + mi * 16 + lr + h * 8;
                float v0 = acc[mi][ni][2 * h]     + bv0;
                float v1 = acc[mi][ni][2 * h + 1] + bv1;
                if (SWISH) {
                    float s0 = fmaf(-0.0208f * v0 * v0, v0, fmaf(0.25f, v0, 0.5f));
                    float s1 = fmaf(-0.0208f * v1 * v1, v1, fmaf(0.25f, v1, 0.5f));
                    v0 *= s0; v1 *= s1;
                }
                if (ROUND_OUT) {
                    asm("cvt.rn.tf32.f32 %0, %0;" : "+f"(v0));
                    asm("cvt.rn.tf32.f32 %0, %0;" : "+f"(v1));
                }
                *reinterpret_cast<float2*>(C + (size_t)row * N + col) =
                    make_float2(v0, v1);
            }
        }
    }
}

// ------------------------- tf32 rounding pre-pass ---------------------------

__global__ void round_tf32_kernel(const float4* __restrict__ in,
                                  float4* __restrict__ out, int n4)
{
    int i = blockIdx.x * blockDim.x + threadIdx.x;
    if (i < n4) {
        float4 v = in[i];
        asm("cvt.rn.tf32.f32 %0, %0;" : "+f"(v.x));
        asm("cvt.rn.tf32.f32 %0, %0;" : "+f"(v.y));
        asm("cvt.rn.tf32.f32 %0, %0;" : "+f"(v.z));
        asm("cvt.rn.tf32.f32 %0, %0;" : "+f"(v.w));
        out[i] = v;
    }
}

// ------------------------------- launch -------------------------------------

extern "C" void kernel_launch(void* const* d_in, const int* in_sizes, int n_in,
                              void* d_out, int out_size)
{
    const float* X  = (const float*)d_in[0]; // [M, D]
    const float* W1 = (const float*)d_in[1]; // [F, D]
    const float* b1 = (const float*)d_in[2]; // [F]
    const float* W2 = (const float*)d_in[3]; // [D, F]
    const float* b2 = (const float*)d_in[4]; // [D]
    float* out = (float*)d_out;              // [M, D]

    const int F = in_sizes[2];               // 4096
    const int D = in_sizes[4];               // 1024
    const int M = in_sizes[0] / D;           // 8192

    float *mid, *Xr, *W1r, *W2r;
    cudaGetSymbolAddress((void**)&mid, g_mid);
    cudaGetSymbolAddress((void**)&Xr,  g_Xr);
    cudaGetSymbolAddress((void**)&W1r, g_W1r);
    cudaGetSymbolAddress((void**)&W2r, g_W2r);

    cudaFuncSetAttribute(ffn_gemm<true,  true >,
                         cudaFuncAttributeMaxDynamicSharedMemorySize, SMEM_DYN);
    cudaFuncSetAttribute(ffn_gemm<false, false>,
                         cudaFuncAttributeMaxDynamicSharedMemorySize, SMEM_DYN);

    // Round inputs to tf32 (RN) so MMA truncation is zero-mean.
    int n4;
    n4 = (M * D) / 4;
    round_tf32_kernel<<<(n4 + 255) / 256, 256>>>((const float4*)X,  (float4*)Xr,  n4);
    n4 = (F * D) / 4;
    round_tf32_kernel<<<(n4 + 255) / 256, 256>>>((const float4*)W1, (float4*)W1r, n4);
    n4 = (D * F) / 4;
    round_tf32_kernel<<<(n4 + 255) / 256, 256>>>((const float4*)W2, (float4*)W2r, n4);

    // GEMM1: mid = round_tf32(swish(X @ W1^T + b1))   [M, F], K = D
    {
        dim3 grid(F / BN, M / BM);
        ffn_gemm<true, true><<<grid, NTHREADS, SMEM_DYN>>>(Xr, W1r, b1, mid, M, F, D);
    }
    // GEMM2: out = mid @ W2^T + b2                    [M, D], K = F
    {
        dim3 grid(D / BN, M / BM);
        ffn_gemm<false, false><<<grid, NTHREADS, SMEM_DYN>>>(mid, W2r, b2, out, M, D, F);
    }
}

// round 9
// speedup vs baseline: 1.3172x; 1.1514x over previous
#include <cuda_runtime.h>
#include <cstdint>

// SecureSwishFeedForward via legacy TF32 mma.sync (m16n8k8).
// (Harness PTX stage targets compute_103 — no tcgen05.)
//
// out = swish_poly(X @ W1^T + b1) @ W2^T + b2
// X:[8192,1024] W1:[4096,1024] W2:[1024,4096], fp32 row-major, K contiguous.
//
// R9: cross-barrier fragment prefetch. Iteration structure:
//   [entry: k0 fragments of stage c already in regs]
//   issue cp.async for stage c+2 ; commit
//   k8=0..3: prefetch k8+1 fragments, 16 HMMAs
//   cp.async.wait_group 0 ; __syncthreads
//   LDSM-prefetch k0 fragments of stage c+1   <- hides LDS latency + sync skew
// Incremental global pointers (advance BK per iter) to cut ALU address math.

#define BM 128
#define BN 128
#define BK 32
#define PAD 4
#define LDSS (BK + PAD)                      // 36 floats
#define A_STAGE_F (BM * LDSS)                // floats per A stage (4608)
#define STAGE_F   (2 * A_STAGE_F)            // floats per stage (9216)
#define STAGE_BYTES (STAGE_F * 4)            // 36864
#define STAGES 3
#define NTHREADS 256
#define SMEM_DYN (STAGES * STAGE_BYTES)      // 110592 bytes

__device__ float g_mid[8192UL * 4096UL];
__device__ float g_Xr [8192UL * 1024UL];
__device__ float g_W1r[4096UL * 1024UL];
__device__ float g_W2r[1024UL * 4096UL];

__device__ __forceinline__ uint32_t stou(const void* p) {
    uint32_t a;
    asm("{ .reg .u64 t; cvta.to.shared.u64 t, %1; cvt.u32.u64 %0, t; }"
        : "=r"(a) : "l"(p));
    return a;
}

__device__ __forceinline__ void cpa16(const float* smem_dst, const float* gsrc) {
    uint32_t a = stou(smem_dst);
    asm volatile("cp.async.cg.shared.global [%0], [%1], 16;" :: "r"(a), "l"(gsrc));
}

// ldmatrix x4 (b16 path, 32-bit payload): lane gets element (lane/4, lane%4)
// of each 8x4-float matrix — the tf32 m16n8k8 fragment layout.
#define LDSM4(r, addr) \
    asm volatile("ldmatrix.sync.aligned.m8n8.x4.shared.b16 {%0,%1,%2,%3}, [%4];" \
                 : "=r"((r)[0]), "=r"((r)[1]), "=r"((r)[2]), "=r"((r)[3])       \
                 : "r"(addr))

template<bool SWISH, bool ROUND_OUT>
__global__ __launch_bounds__(NTHREADS, 2)
void ffn_gemm(const float* __restrict__ A,    // [M, K] tf32-rounded
              const float* __restrict__ B,    // [N, K] tf32-rounded
              const float* __restrict__ bias, // [N]
              float* __restrict__ C,          // [M, N]
              int M, int N, int K)
{
    extern __shared__ __align__(16) float smem[];
    const uint32_t smem_u32 = stou(smem);

    const int tid  = threadIdx.x;
    const int wid  = tid >> 5, lane = tid & 31;
    const int wr   = wid >> 2, wc   = wid & 3;   // 2x4 warp grid -> 64x32 warp tile
    const int lr   = lane >> 2, lc  = lane & 3;
    const int rowBase = blockIdx.y * BM;
    const int colBase = blockIdx.x * BN;
    const int NC = K / BK;

    const int t8  = lane & 7;
    const int tb3 = (lane >> 3) & 1;
    const int tb4 = (lane >> 4) & 1;
    uint32_t a_off[4], b_off[2];
#pragma unroll
    for (int mi = 0; mi < 4; mi++)
        a_off[mi] = (uint32_t)(((wr * 64 + mi * 16 + t8 + tb3 * 8) * LDSS + tb4 * 4) * 4);
#pragma unroll
    for (int p = 0; p < 2; p++)
        b_off[p] = (uint32_t)((A_STAGE_F + (wc * 32 + p * 16 + t8 + tb4 * 8) * LDSS + tb3 * 4) * 4);

    float acc[4][4][4];
#pragma unroll
    for (int mi = 0; mi < 4; mi++)
#pragma unroll
        for (int ni = 0; ni < 4; ni++)
#pragma unroll
            for (int e = 0; e < 4; e++) acc[mi][ni][e] = 0.0f;

    // Per-thread incremental gmem pointers (advance BK per stage).
    const int ldrow = tid >> 3;
    const int ldq   = (tid & 7) * 4;
    const float* aLd = A + (size_t)(rowBase + ldrow) * K + ldq;
    const float* bLd = B + (size_t)(colBase + ldrow) * K + ldq;

    #define LOAD_STAGE(s, aP, bP) do {                                         \
        float* sa_ = smem + (s) * STAGE_F;                                     \
        float* sb_ = sa_ + A_STAGE_F;                                          \
        _Pragma("unroll")                                                      \
        for (int it_ = 0; it_ < 4; it_++)                                      \
            cpa16(sa_ + (ldrow + it_ * 32) * LDSS + ldq,                       \
                  (aP) + (size_t)(it_ * 32) * K);                              \
        _Pragma("unroll")                                                      \
        for (int it_ = 0; it_ < 4; it_++)                                      \
            cpa16(sb_ + (ldrow + it_ * 32) * LDSS + ldq,                       \
                  (bP) + (size_t)(it_ * 32) * K);                              \
    } while (0)

    #define LOADK(sb_addr, k8, afb, bfb) do {                                  \
        _Pragma("unroll")                                                      \
        for (int mi_ = 0; mi_ < 4; mi_++)                                      \
            LDSM4((afb)[mi_], (sb_addr) + a_off[mi_] + (k8) * 32);             \
        _Pragma("unroll")                                                      \
        for (int p_ = 0; p_ < 2; p_++)                                         \
            LDSM4((bfb)[p_], (sb_addr) + b_off[p_] + (k8) * 32);               \
    } while (0)

    #define DO_MMAS(afb, bfb) do {                                             \
        _Pragma("unroll")                                                      \
        for (int mi_ = 0; mi_ < 4; mi_++)                                      \
            _Pragma("unroll")                                                  \
            for (int ni_ = 0; ni_ < 4; ni_++)                                  \
                asm volatile(                                                  \
                    "mma.sync.aligned.m16n8k8.row.col.f32.tf32.tf32.f32 "      \
                    "{%0,%1,%2,%3}, {%4,%5,%6,%7}, {%8,%9}, {%0,%1,%2,%3};"    \
                    : "+f"(acc[mi_][ni_][0]), "+f"(acc[mi_][ni_][1]),          \
                      "+f"(acc[mi_][ni_][2]), "+f"(acc[mi_][ni_][3])           \
                    : "r"((afb)[mi_][0]), "r"((afb)[mi_][1]),                  \
                      "r"((afb)[mi_][2]), "r"((afb)[mi_][3]),                  \
                      "r"((bfb)[ni_ >> 1][(ni_ & 1) * 2]),                     \
                      "r"((bfb)[ni_ >> 1][(ni_ & 1) * 2 + 1]));                \
    } while (0)

    // Prologue: load stages 0 and 1, wait both, prefetch iter-0 k0 fragments.
    LOAD_STAGE(0, aLd, bLd); aLd += BK; bLd += BK;
    asm volatile("cp.async.commit_group;" ::: "memory");
    LOAD_STAGE(1, aLd, bLd); aLd += BK; bLd += BK;
    asm volatile("cp.async.commit_group;" ::: "memory");
    asm volatile("cp.async.wait_group 0;" ::: "memory");
    __syncthreads();

    uint32_t af[2][4][4], bf[2][2][4];
    LOADK(smem_u32, 0, af[0], bf[0]);

    for (int c = 0; c < NC; c++) {
        const uint32_t sbase = smem_u32 + (c % STAGES) * STAGE_BYTES;

        // Issue next-next stage loads; they complete during this MMA section.
        if (c + 2 < NC) {
            LOAD_STAGE((c + 2) % STAGES, aLd, bLd);
            aLd += BK; bLd += BK;
        }
        asm volatile("cp.async.commit_group;" ::: "memory");

#pragma unroll
        for (int k8 = 0; k8 < 4; k8++) {
            const int cur = k8 & 1;
            if (k8 < 3) LOADK(sbase, k8 + 1, af[cur ^ 1], bf[cur ^ 1]);
            DO_MMAS(af[cur], bf[cur]);
        }

        // Drain the in-flight group, make all copies CTA-visible, then
        // prefetch next iteration's k0 fragments so HMMAs restart instantly.
        asm volatile("cp.async.wait_group 0;" ::: "memory");
        __syncthreads();
        if (c + 1 < NC) {
            const uint32_t snext = smem_u32 + ((c + 1) % STAGES) * STAGE_BYTES;
            LOADK(snext, 0, af[0], bf[0]);
        }
    }

    // Epilogue: bias + optional poly-swish (+ optional tf32 re-round).
#pragma unroll
    for (int ni = 0; ni < 4; ni++) {
        const int col = colBase + wc * 32 + ni * 8 + 2 * lc;
        const float bv0 = __ldg(bias + col);
        const float bv1 = __ldg(bias + col + 1);
#pragma unroll
        for (int mi = 0; mi < 4; mi++) {
#pragma unroll
            for (int h = 0; h < 2; h++) {
                const int row = rowBase + wr * 64 + mi * 16 + lr + h * 8;
                float v0 = acc[mi][ni][2 * h]     + bv0;
                float v1 = acc[mi][ni][2 * h + 1] + bv1;
                if (SWISH) {
                    float s0 = fmaf(-0.0208f * v0 * v0, v0, fmaf(0.25f, v0, 0.5f));
                    float s1 = fmaf(-0.0208f * v1 * v1, v1, fmaf(0.25f, v1, 0.5f));
                    v0 *= s0; v1 *= s1;
                }
                if (ROUND_OUT) {
                    asm("cvt.rn.tf32.f32 %0, %0;" : "+f"(v0));
                    asm("cvt.rn.tf32.f32 %0, %0;" : "+f"(v1));
                }
                *reinterpret_cast<float2*>(C + (size_t)row * N + col) =
                    make_float2(v0, v1);
            }
        }
    }
}

// ------------------------- tf32 rounding pre-pass ---------------------------

__global__ void round_tf32_kernel(const float4* __restrict__ in,
                                  float4* __restrict__ out, int n4)
{
    int i = blockIdx.x * blockDim.x + threadIdx.x;
    if (i < n4) {
        float4 v = in[i];
        asm("cvt.rn.tf32.f32 %0, %0;" : "+f"(v.x));
        asm("cvt.rn.tf32.f32 %0, %0;" : "+f"(v.y));
        asm("cvt.rn.tf32.f32 %0, %0;" : "+f"(v.z));
        asm("cvt.rn.tf32.f32 %0, %0;" : "+f"(v.w));
        out[i] = v;
    }
}

// ------------------------------- launch -------------------------------------

extern "C" void kernel_launch(void* const* d_in, const int* in_sizes, int n_in,
                              void* d_out, int out_size)
{
    const float* X  = (const float*)d_in[0]; // [M, D]
    const float* W1 = (const float*)d_in[1]; // [F, D]
    const float* b1 = (const float*)d_in[2]; // [F]
    const float* W2 = (const float*)d_in[3]; // [D, F]
    const float* b2 = (const float*)d_in[4]; // [D]
    float* out = (float*)d_out;              // [M, D]

    const int F = in_sizes[2];               // 4096
    const int D = in_sizes[4];               // 1024
    const int M = in_sizes[0] / D;           // 8192

    float *mid, *Xr, *W1r, *W2r;
    cudaGetSymbolAddress((void**)&mid, g_mid);
    cudaGetSymbolAddress((void**)&Xr,  g_Xr);
    cudaGetSymbolAddress((void**)&W1r, g_W1r);
    cudaGetSymbolAddress((void**)&W2r, g_W2r);

    cudaFuncSetAttribute(ffn_gemm<true,  true >,
                         cudaFuncAttributeMaxDynamicSharedMemorySize, SMEM_DYN);
    cudaFuncSetAttribute(ffn_gemm<false, false>,
                         cudaFuncAttributeMaxDynamicSharedMemorySize, SMEM_DYN);

    // Round inputs to tf32 (RN) so MMA truncation is zero-mean.
    int n4;
    n4 = (M * D) / 4;
    round_tf32_kernel<<<(n4 + 255) / 256, 256>>>((const float4*)X,  (float4*)Xr,  n4);
    n4 = (F * D) / 4;
    round_tf32_kernel<<<(n4 + 255) / 256, 256>>>((const float4*)W1, (float4*)W1r, n4);
    n4 = (D * F) / 4;
    round_tf32_kernel<<<(n4 + 255) / 256, 256>>>((const float4*)W2, (float4*)W2r, n4);

    // GEMM1: mid = round_tf32(swish(X @ W1^T + b1))   [M, F], K = D
    {
        dim3 grid(F / BN, M / BM);
        ffn_gemm<true, true><<<grid, NTHREADS, SMEM_DYN>>>(Xr, W1r, b1, mid, M, F, D);
    }
    // GEMM2: out = mid @ W2^T + b2                    [M, D], K = F
    {
        dim3 grid(D / BN, M / BM);
        ffn_gemm<false, false><<<grid, NTHREADS, SMEM_DYN>>>(mid, W2r, b2, out, M, D, F);
    }
}

// round 10
// speedup vs baseline: 1.3527x; 1.0270x over previous
#include <cuda_runtime.h>
#include <cstdint>

// SecureSwishFeedForward via legacy TF32 mma.sync (m16n8k8).
// (Harness PTX stage targets compute_103 — no tcgen05.)
//
// out = swish_poly(X @ W1^T + b1) @ W2^T + b2
// X:[8192,1024] W1:[4096,1024] W2:[1024,4096], fp32 row-major, K contiguous.
//
// R10: relax the iteration-bottom drain from wait_group 0 to wait_group 1.
// At bottom of iter c the in-flight groups are {c+1, c+2}; the post-barrier
// fragment prefetch only needs stage c+1 -> waiting all-but-one gives the
// stage c+2 load a full extra iteration of latency slack.

#define BM 128
#define BN 128
#define BK 32
#define PAD 4
#define LDSS (BK + PAD)                      // 36 floats
#define A_STAGE_F (BM * LDSS)                // floats per A stage (4608)
#define STAGE_F   (2 * A_STAGE_F)            // floats per stage (9216)
#define STAGE_BYTES (STAGE_F * 4)            // 36864
#define STAGES 3
#define NTHREADS 256
#define SMEM_DYN (STAGES * STAGE_BYTES)      // 110592 bytes

__device__ float g_mid[8192UL * 4096UL];
__device__ float g_Xr [8192UL * 1024UL];
__device__ float g_W1r[4096UL * 1024UL];
__device__ float g_W2r[1024UL * 4096UL];

__device__ __forceinline__ uint32_t stou(const void* p) {
    uint32_t a;
    asm("{ .reg .u64 t; cvta.to.shared.u64 t, %1; cvt.u32.u64 %0, t; }"
        : "=r"(a) : "l"(p));
    return a;
}

__device__ __forceinline__ void cpa16(const float* smem_dst, const float* gsrc) {
    uint32_t a = stou(smem_dst);
    asm volatile("cp.async.cg.shared.global [%0], [%1], 16;" :: "r"(a), "l"(gsrc));
}

// ldmatrix x4 (b16 path, 32-bit payload): lane gets element (lane/4, lane%4)
// of each 8x4-float matrix — the tf32 m16n8k8 fragment layout.
#define LDSM4(r, addr) \
    asm volatile("ldmatrix.sync.aligned.m8n8.x4.shared.b16 {%0,%1,%2,%3}, [%4];" \
                 : "=r"((r)[0]), "=r"((r)[1]), "=r"((r)[2]), "=r"((r)[3])       \
                 : "r"(addr))

template<bool SWISH, bool ROUND_OUT>
__global__ __launch_bounds__(NTHREADS, 2)
void ffn_gemm(const float* __restrict__ A,    // [M, K] tf32-rounded
              const float* __restrict__ B,    // [N, K] tf32-rounded
              const float* __restrict__ bias, // [N]
              float* __restrict__ C,          // [M, N]
              int M, int N, int K)
{
    extern __shared__ __align__(16) float smem[];
    const uint32_t smem_u32 = stou(smem);

    const int tid  = threadIdx.x;
    const int wid  = tid >> 5, lane = tid & 31;
    const int wr   = wid >> 2, wc   = wid & 3;   // 2x4 warp grid -> 64x32 warp tile
    const int lr   = lane >> 2, lc  = lane & 3;
    const int rowBase = blockIdx.y * BM;
    const int colBase = blockIdx.x * BN;
    const int NC = K / BK;

    const int t8  = lane & 7;
    const int tb3 = (lane >> 3) & 1;
    const int tb4 = (lane >> 4) & 1;
    uint32_t a_off[4], b_off[2];
#pragma unroll
    for (int mi = 0; mi < 4; mi++)
        a_off[mi] = (uint32_t)(((wr * 64 + mi * 16 + t8 + tb3 * 8) * LDSS + tb4 * 4) * 4);
#pragma unroll
    for (int p = 0; p < 2; p++)
        b_off[p] = (uint32_t)((A_STAGE_F + (wc * 32 + p * 16 + t8 + tb4 * 8) * LDSS + tb3 * 4) * 4);

    float acc[4][4][4];
#pragma unroll
    for (int mi = 0; mi < 4; mi++)
#pragma unroll
        for (int ni = 0; ni < 4; ni++)
#pragma unroll
            for (int e = 0; e < 4; e++) acc[mi][ni][e] = 0.0f;

    // Per-thread incremental gmem pointers (advance BK per stage).
    const int ldrow = tid >> 3;
    const int ldq   = (tid & 7) * 4;
    const float* aLd = A + (size_t)(rowBase + ldrow) * K + ldq;
    const float* bLd = B + (size_t)(colBase + ldrow) * K + ldq;

    #define LOAD_STAGE(s, aP, bP) do {                                         \
        float* sa_ = smem + (s) * STAGE_F;                                     \
        float* sb_ = sa_ + A_STAGE_F;                                          \
        _Pragma("unroll")                                                      \
        for (int it_ = 0; it_ < 4; it_++)                                      \
            cpa16(sa_ + (ldrow + it_ * 32) * LDSS + ldq,                       \
                  (aP) + (size_t)(it_ * 32) * K);                              \
        _Pragma("unroll")                                                      \
        for (int it_ = 0; it_ < 4; it_++)                                      \
            cpa16(sb_ + (ldrow + it_ * 32) * LDSS + ldq,                       \
                  (bP) + (size_t)(it_ * 32) * K);                              \
    } while (0)

    #define LOADK(sb_addr, k8, afb, bfb) do {                                  \
        _Pragma("unroll")                                                      \
        for (int mi_ = 0; mi_ < 4; mi_++)                                      \
            LDSM4((afb)[mi_], (sb_addr) + a_off[mi_] + (k8) * 32);             \
        _Pragma("unroll")                                                      \
        for (int p_ = 0; p_ < 2; p_++)                                         \
            LDSM4((bfb)[p_], (sb_addr) + b_off[p_] + (k8) * 32);               \
    } while (0)

    #define DO_MMAS(afb, bfb) do {                                             \
        _Pragma("unroll")                                                      \
        for (int mi_ = 0; mi_ < 4; mi_++)                                      \
            _Pragma("unroll")                                                  \
            for (int ni_ = 0; ni_ < 4; ni_++)                                  \
                asm volatile(                                                  \
                    "mma.sync.aligned.m16n8k8.row.col.f32.tf32.tf32.f32 "      \
                    "{%0,%1,%2,%3}, {%4,%5,%6,%7}, {%8,%9}, {%0,%1,%2,%3};"    \
                    : "+f"(acc[mi_][ni_][0]), "+f"(acc[mi_][ni_][1]),          \
                      "+f"(acc[mi_][ni_][2]), "+f"(acc[mi_][ni_][3])           \
                    : "r"((afb)[mi_][0]), "r"((afb)[mi_][1]),                  \
                      "r"((afb)[mi_][2]), "r"((afb)[mi_][3]),                  \
                      "r"((bfb)[ni_ >> 1][(ni_ & 1) * 2]),                     \
                      "r"((bfb)[ni_ >> 1][(ni_ & 1) * 2 + 1]));                \
    } while (0)

    // Prologue: load stages 0 and 1; wait for stage 0 only (all-but-one),
    // barrier, prefetch iter-0 k0 fragments.
    LOAD_STAGE(0, aLd, bLd); aLd += BK; bLd += BK;
    asm volatile("cp.async.commit_group;" ::: "memory");
    LOAD_STAGE(1, aLd, bLd); aLd += BK; bLd += BK;
    asm volatile("cp.async.commit_group;" ::: "memory");
    asm volatile("cp.async.wait_group 1;" ::: "memory");
    __syncthreads();

    uint32_t af[2][4][4], bf[2][2][4];
    LOADK(smem_u32, 0, af[0], bf[0]);

    for (int c = 0; c < NC; c++) {
        const uint32_t sbase = smem_u32 + (c % STAGES) * STAGE_BYTES;

        // Issue next-next stage loads; they have ~2 iterations to complete.
        if (c + 2 < NC) {
            LOAD_STAGE((c + 2) % STAGES, aLd, bLd);
            aLd += BK; bLd += BK;
        }
        asm volatile("cp.async.commit_group;" ::: "memory");

#pragma unroll
        for (int k8 = 0; k8 < 4; k8++) {
            const int cur = k8 & 1;
            if (k8 < 3) LOADK(sbase, k8 + 1, af[cur ^ 1], bf[cur ^ 1]);
            DO_MMAS(af[cur], bf[cur]);
        }

        // In-flight: groups {c+1, c+2}. Wait all-but-one -> stage c+1 ready;
        // stage c+2 keeps flying through the next iteration.
        asm volatile("cp.async.wait_group 1;" ::: "memory");
        __syncthreads();
        if (c + 1 < NC) {
            const uint32_t snext = smem_u32 + ((c + 1) % STAGES) * STAGE_BYTES;
            LOADK(snext, 0, af[0], bf[0]);
        }
    }

    // Epilogue: bias + optional poly-swish (+ optional tf32 re-round).
#pragma unroll
    for (int ni = 0; ni < 4; ni++) {
        const int col = colBase + wc * 32 + ni * 8 + 2 * lc;
        const float bv0 = __ldg(bias + col);
        const float bv1 = __ldg(bias + col + 1);
#pragma unroll
        for (int mi = 0; mi < 4; mi++) {
#pragma unroll
            for (int h = 0; h < 2; h++) {
                const int row = rowBase + wr * 64 + mi * 16 + lr + h * 8;
                float v0 = acc[mi][ni][2 * h]     + bv0;
                float v1 = acc[mi][ni][2 * h + 1] + bv1;
                if (SWISH) {
                    float s0 = fmaf(-0.0208f * v0 * v0, v0, fmaf(0.25f, v0, 0.5f));
                    float s1 = fmaf(-0.0208f * v1 * v1, v1, fmaf(0.25f, v1, 0.5f));
                    v0 *= s0; v1 *= s1;
                }
                if (ROUND_OUT) {
                    asm("cvt.rn.tf32.f32 %0, %0;" : "+f"(v0));
                    asm("cvt.rn.tf32.f32 %0, %0;" : "+f"(v1));
                }
                *reinterpret_cast<float2*>(C + (size_t)row * N + col) =
                    make_float2(v0, v1);
            }
        }
    }
}

// ------------------------- tf32 rounding pre-pass ---------------------------

__global__ void round_tf32_kernel(const float4* __restrict__ in,
                                  float4* __restrict__ out, int n4)
{
    int i = blockIdx.x * blockDim.x + threadIdx.x;
    if (i < n4) {
        float4 v = in[i];
        asm("cvt.rn.tf32.f32 %0, %0;" : "+f"(v.x));
        asm("cvt.rn.tf32.f32 %0, %0;" : "+f"(v.y));
        asm("cvt.rn.tf32.f32 %0, %0;" : "+f"(v.z));
        asm("cvt.rn.tf32.f32 %0, %0;" : "+f"(v.w));
        out[i] = v;
    }
}

// ------------------------------- launch -------------------------------------

extern "C" void kernel_launch(void* const* d_in, const int* in_sizes, int n_in,
                              void* d_out, int out_size)
{
    const float* X  = (const float*)d_in[0]; // [M, D]
    const float* W1 = (const float*)d_in[1]; // [F, D]
    const float* b1 = (const float*)d_in[2]; // [F]
    const float* W2 = (const float*)d_in[3]; // [D, F]
    const float* b2 = (const float*)d_in[4]; // [D]
    float* out = (float*)d_out;              // [M, D]

    const int F = in_sizes[2];               // 4096
    const int D = in_sizes[4];               // 1024
    const int M = in_sizes[0] / D;           // 8192

    float *mid, *Xr, *W1r, *W2r;
    cudaGetSymbolAddress((void**)&mid, g_mid);
    cudaGetSymbolAddress((void**)&Xr,  g_Xr);
    cudaGetSymbolAddress((void**)&W1r, g_W1r);
    cudaGetSymbolAddress((void**)&W2r, g_W2r);

    cudaFuncSetAttribute(ffn_gemm<true,  true >,
                         cudaFuncAttributeMaxDynamicSharedMemorySize, SMEM_DYN);
    cudaFuncSetAttribute(ffn_gemm<false, false>,
                         cudaFuncAttributeMaxDynamicSharedMemorySize, SMEM_DYN);

    // Round inputs to tf32 (RN) so MMA truncation is zero-mean.
    int n4;
    n4 = (M * D) / 4;
    round_tf32_kernel<<<(n4 + 255) / 256, 256>>>((const float4*)X,  (float4*)Xr,  n4);
    n4 = (F * D) / 4;
    round_tf32_kernel<<<(n4 + 255) / 256, 256>>>((const float4*)W1, (float4*)W1r, n4);
    n4 = (D * F) / 4;
    round_tf32_kernel<<<(n4 + 255) / 256, 256>>>((const float4*)W2, (float4*)W2r, n4);

    // GEMM1: mid = round_tf32(swish(X @ W1^T + b1))   [M, F], K = D
    {
        dim3 grid(F / BN, M / BM);
        ffn_gemm<true, true><<<grid, NTHREADS, SMEM_DYN>>>(Xr, W1r, b1, mid, M, F, D);
    }
    // GEMM2: out = mid @ W2^T + b2                    [M, D], K = F
    {
        dim3 grid(D / BN, M / BM);
        ffn_gemm<false, false><<<grid, NTHREADS, SMEM_DYN>>>(mid, W2r, b2, out, M, D, F);
    }
}

// round 11
// speedup vs baseline: 1.4496x; 1.0716x over previous
#include <cuda_runtime.h>
#include <cstdint>

// SecureSwishFeedForward via legacy TF32 mma.sync (m16n8k8).
// (Harness PTX stage targets compute_103 — no tcgen05.)
//
// out = swish_poly(X @ W1^T + b1) @ W2^T + b2
// X:[8192,1024] W1:[4096,1024] W2:[1024,4096], fp32 row-major, K contiguous.
//
// R11: register relief + issue reordering.
//  - A fragments single-buffered, JIT-reloaded right after their 4 HMMAs
//    issue (WAR safe via scoreboard) -> saves 16 regs, kills spills at the
//    128-reg occ-2 cap.
//  - next-stage cp.async issue moved after k8=0's MMAs so the tensor pipe
//    restarts immediately after the barrier.
//  - single fused tf32-rounding pre-pass kernel.

#define BM 128
#define BN 128
#define BK 32
#define PAD 4
#define LDSS (BK + PAD)                      // 36 floats
#define A_STAGE_F (BM * LDSS)                // floats per A stage (4608)
#define STAGE_F   (2 * A_STAGE_F)            // floats per stage (9216)
#define STAGE_BYTES (STAGE_F * 4)            // 36864
#define STAGES 3
#define NTHREADS 256
#define SMEM_DYN (STAGES * STAGE_BYTES)      // 110592 bytes

__device__ float g_mid[8192UL * 4096UL];
__device__ float g_Xr [8192UL * 1024UL];
__device__ float g_W1r[4096UL * 1024UL];
__device__ float g_W2r[1024UL * 4096UL];

__device__ __forceinline__ uint32_t stou(const void* p) {
    uint32_t a;
    asm("{ .reg .u64 t; cvta.to.shared.u64 t, %1; cvt.u32.u64 %0, t; }"
        : "=r"(a) : "l"(p));
    return a;
}

__device__ __forceinline__ void cpa16(const float* smem_dst, const float* gsrc) {
    uint32_t a = stou(smem_dst);
    asm volatile("cp.async.cg.shared.global [%0], [%1], 16;" :: "r"(a), "l"(gsrc));
}

// ldmatrix x4 (b16 path, 32-bit payload): lane gets element (lane/4, lane%4)
// of each 8x4-float matrix — the tf32 m16n8k8 fragment layout.
#define LDSM4(r, addr) \
    asm volatile("ldmatrix.sync.aligned.m8n8.x4.shared.b16 {%0,%1,%2,%3}, [%4];" \
                 : "=r"((r)[0]), "=r"((r)[1]), "=r"((r)[2]), "=r"((r)[3])       \
                 : "r"(addr))

template<bool SWISH, bool ROUND_OUT>
__global__ __launch_bounds__(NTHREADS, 2)
void ffn_gemm(const float* __restrict__ A,    // [M, K] tf32-rounded
              const float* __restrict__ B,    // [N, K] tf32-rounded
              const float* __restrict__ bias, // [N]
              float* __restrict__ C,          // [M, N]
              int M, int N, int K)
{
    extern __shared__ __align__(16) float smem[];
    const uint32_t smem_u32 = stou(smem);

    const int tid  = threadIdx.x;
    const int wid  = tid >> 5, lane = tid & 31;
    const int wr   = wid >> 2, wc   = wid & 3;   // 2x4 warp grid -> 64x32 warp tile
    const int lr   = lane >> 2, lc  = lane & 3;
    const int rowBase = blockIdx.y * BM;
    const int colBase = blockIdx.x * BN;
    const int NC = K / BK;

    const int t8  = lane & 7;
    const int tb3 = (lane >> 3) & 1;
    const int tb4 = (lane >> 4) & 1;
    uint32_t a_off[4], b_off[2];
#pragma unroll
    for (int mi = 0; mi < 4; mi++)
        a_off[mi] = (uint32_t)(((wr * 64 + mi * 16 + t8 + tb3 * 8) * LDSS + tb4 * 4) * 4);
#pragma unroll
    for (int p = 0; p < 2; p++)
        b_off[p] = (uint32_t)((A_STAGE_F + (wc * 32 + p * 16 + t8 + tb4 * 8) * LDSS + tb3 * 4) * 4);

    float acc[4][4][4];
#pragma unroll
    for (int mi = 0; mi < 4; mi++)
#pragma unroll
        for (int ni = 0; ni < 4; ni++)
#pragma unroll
            for (int e = 0; e < 4; e++) acc[mi][ni][e] = 0.0f;

    // Per-thread incremental gmem pointers (advance BK per stage).
    const int ldrow = tid >> 3;
    const int ldq   = (tid & 7) * 4;
    const float* aLd = A + (size_t)(rowBase + ldrow) * K + ldq;
    const float* bLd = B + (size_t)(colBase + ldrow) * K + ldq;

    #define LOAD_STAGE(s, aP, bP) do {                                         \
        float* sa_ = smem + (s) * STAGE_F;                                     \
        float* sb_ = sa_ + A_STAGE_F;                                          \
        _Pragma("unroll")                                                      \
        for (int it_ = 0; it_ < 4; it_++)                                      \
            cpa16(sa_ + (ldrow + it_ * 32) * LDSS + ldq,                       \
                  (aP) + (size_t)(it_ * 32) * K);                              \
        _Pragma("unroll")                                                      \
        for (int it_ = 0; it_ < 4; it_++)                                      \
            cpa16(sb_ + (ldrow + it_ * 32) * LDSS + ldq,                       \
                  (bP) + (size_t)(it_ * 32) * K);                              \
    } while (0)

    #define LOADA_ONE(sb_addr, k8, mi_, afb) \
        LDSM4((afb)[mi_], (sb_addr) + a_off[mi_] + (k8) * 32)

    #define LOADB(sb_addr, k8, bfb) do {                                       \
        _Pragma("unroll")                                                      \
        for (int p_ = 0; p_ < 2; p_++)                                         \
            LDSM4((bfb)[p_], (sb_addr) + b_off[p_] + (k8) * 32);               \
    } while (0)

    #define MMA_ROW(mi_, afrag, bfb) do {                                      \
        _Pragma("unroll")                                                      \
        for (int ni_ = 0; ni_ < 4; ni_++)                                      \
            asm volatile(                                                      \
                "mma.sync.aligned.m16n8k8.row.col.f32.tf32.tf32.f32 "          \
                "{%0,%1,%2,%3}, {%4,%5,%6,%7}, {%8,%9}, {%0,%1,%2,%3};"        \
                : "+f"(acc[mi_][ni_][0]), "+f"(acc[mi_][ni_][1]),              \
                  "+f"(acc[mi_][ni_][2]), "+f"(acc[mi_][ni_][3])               \
                : "r"((afrag)[0]), "r"((afrag)[1]),                            \
                  "r"((afrag)[2]), "r"((afrag)[3]),                            \
                  "r"((bfb)[ni_ >> 1][(ni_ & 1) * 2]),                         \
                  "r"((bfb)[ni_ >> 1][(ni_ & 1) * 2 + 1]));                    \
    } while (0)

    // Prologue: load stages 0 and 1; wait stage 0, barrier, prefetch k0 frags.
    LOAD_STAGE(0, aLd, bLd); aLd += BK; bLd += BK;
    asm volatile("cp.async.commit_group;" ::: "memory");
    LOAD_STAGE(1, aLd, bLd); aLd += BK; bLd += BK;
    asm volatile("cp.async.commit_group;" ::: "memory");
    asm volatile("cp.async.wait_group 1;" ::: "memory");
    __syncthreads();

    uint32_t af[4][4];            // A: single-buffered, JIT reloaded
    uint32_t bf[2][2][4];         // B: double-buffered
#pragma unroll
    for (int mi = 0; mi < 4; mi++) LOADA_ONE(smem_u32, 0, mi, af);
    LOADB(smem_u32, 0, bf[0]);

    for (int c = 0; c < NC; c++) {
        const uint32_t sbase = smem_u32 + (c % STAGES) * STAGE_BYTES;
        const bool haveNextStage = (c + 2 < NC);

#pragma unroll
        for (int k8 = 0; k8 < 4; k8++) {
            const int cur = k8 & 1;
            if (k8 < 3) LOADB(sbase, k8 + 1, bf[cur ^ 1]);
#pragma unroll
            for (int mi = 0; mi < 4; mi++) {
                MMA_ROW(mi, af[mi], bf[cur]);
                // JIT reload af[mi] for next k8 (WAR resolved by scoreboard;
                // result needed only after the remaining rows' MMAs).
                if (k8 < 3) LOADA_ONE(sbase, k8 + 1, mi, af);
            }
            // Issue next-next stage gmem loads AFTER the first MMA burst so
            // the tensor pipe restarts immediately post-barrier.
            if (k8 == 0) {
                if (haveNextStage) {
                    LOAD_STAGE((c + 2) % STAGES, aLd, bLd);
                    aLd += BK; bLd += BK;
                }
                asm volatile("cp.async.commit_group;" ::: "memory");
            }
        }

        // In-flight: groups {c+1, c+2}. Wait all-but-one -> stage c+1 ready.
        asm volatile("cp.async.wait_group 1;" ::: "memory");
        __syncthreads();
        if (c + 1 < NC) {
            const uint32_t snext = smem_u32 + ((c + 1) % STAGES) * STAGE_BYTES;
#pragma unroll
            for (int mi = 0; mi < 4; mi++) LOADA_ONE(snext, 0, mi, af);
            LOADB(snext, 0, bf[0]);
        }
    }

    // Epilogue: bias + optional poly-swish (+ optional tf32 re-round).
#pragma unroll
    for (int ni = 0; ni < 4; ni++) {
        const int col = colBase + wc * 32 + ni * 8 + 2 * lc;
        const float bv0 = __ldg(bias + col);
        const float bv1 = __ldg(bias + col + 1);
#pragma unroll
        for (int mi = 0; mi < 4; mi++) {
#pragma unroll
            for (int h = 0; h < 2; h++) {
                const int row = rowBase + wr * 64 + mi * 16 + lr + h * 8;
                float v0 = acc[mi][ni][2 * h]     + bv0;
                float v1 = acc[mi][ni][2 * h + 1] + bv1;
                if (SWISH) {
                    float s0 = fmaf(-0.0208f * v0 * v0, v0, fmaf(0.25f, v0, 0.5f));
                    float s1 = fmaf(-0.0208f * v1 * v1, v1, fmaf(0.25f, v1, 0.5f));
                    v0 *= s0; v1 *= s1;
                }
                if (ROUND_OUT) {
                    asm("cvt.rn.tf32.f32 %0, %0;" : "+f"(v0));
                    asm("cvt.rn.tf32.f32 %0, %0;" : "+f"(v1));
                }
                *reinterpret_cast<float2*>(C + (size_t)row * N + col) =
                    make_float2(v0, v1);
            }
        }
    }
}

// -------------------- fused tf32 rounding pre-pass --------------------------
// One launch covers X (n1 float4s), W1 (n2), W2 (n3), laid out back-to-back
// in index space.

__global__ void round_tf32_fused(const float4* __restrict__ x,  float4* __restrict__ xr,  int n1,
                                 const float4* __restrict__ w1, float4* __restrict__ w1r, int n2,
                                 const float4* __restrict__ w2, float4* __restrict__ w2r, int n3)
{
    int i = blockIdx.x * blockDim.x + threadIdx.x;
    const float4* src; float4* dst; int j;
    if (i < n1)                { src = x;  dst = xr;  j = i; }
    else if (i < n1 + n2)      { src = w1; dst = w1r; j = i - n1; }
    else if (i < n1 + n2 + n3) { src = w2; dst = w2r; j = i - n1 - n2; }
    else return;
    float4 v = src[j];
    asm("cvt.rn.tf32.f32 %0, %0;" : "+f"(v.x));
    asm("cvt.rn.tf32.f32 %0, %0;" : "+f"(v.y));
    asm("cvt.rn.tf32.f32 %0, %0;" : "+f"(v.z));
    asm("cvt.rn.tf32.f32 %0, %0;" : "+f"(v.w));
    dst[j] = v;
}

// ------------------------------- launch -------------------------------------

extern "C" void kernel_launch(void* const* d_in, const int* in_sizes, int n_in,
                              void* d_out, int out_size)
{
    const float* X  = (const float*)d_in[0]; // [M, D]
    const float* W1 = (const float*)d_in[1]; // [F, D]
    const float* b1 = (const float*)d_in[2]; // [F]
    const float* W2 = (const float*)d_in[3]; // [D, F]
    const float* b2 = (const float*)d_in[4]; // [D]
    float* out = (float*)d_out;              // [M, D]

    const int F = in_sizes[2];               // 4096
    const int D = in_sizes[4];               // 1024
    const int M = in_sizes[0] / D;           // 8192

    float *mid, *Xr, *W1r, *W2r;
    cudaGetSymbolAddress((void**)&mid, g_mid);
    cudaGetSymbolAddress((void**)&Xr,  g_Xr);
    cudaGetSymbolAddress((void**)&W1r, g_W1r);
    cudaGetSymbolAddress((void**)&W2r, g_W2r);

    cudaFuncSetAttribute(ffn_gemm<true,  true >,
                         cudaFuncAttributeMaxDynamicSharedMemorySize, SMEM_DYN);
    cudaFuncSetAttribute(ffn_gemm<false, false>,
                         cudaFuncAttributeMaxDynamicSharedMemorySize, SMEM_DYN);

    // Round inputs to tf32 (RN) so MMA truncation is zero-mean. One launch.
    const int n1 = (M * D) / 4, n2 = (F * D) / 4, n3 = (D * F) / 4;
    const int ntot = n1 + n2 + n3;
    round_tf32_fused<<<(ntot + 255) / 256, 256>>>(
        (const float4*)X,  (float4*)Xr,  n1,
        (const float4*)W1, (float4*)W1r, n2,
        (const float4*)W2, (float4*)W2r, n3);

    // GEMM1: mid = round_tf32(swish(X @ W1^T + b1))   [M, F], K = D
    {
        dim3 grid(F / BN, M / BM);
        ffn_gemm<true, true><<<grid, NTHREADS, SMEM_DYN>>>(Xr, W1r, b1, mid, M, F, D);
    }
    // GEMM2: out = mid @ W2^T + b2                    [M, D], K = F
    {
        dim3 grid(D / BN, M / BM);
        ffn_gemm<false, false><<<grid, NTHREADS, SMEM_DYN>>>(mid, W2r, b2, out, M, D, F);
    }
}

// round 13
// speedup vs baseline: 2.6801x; 1.8489x over previous
#include <cuda_runtime.h>
#include <cuda_fp16.h>
#include <cstdint>

// SecureSwishFeedForward via fp16 mma.sync (m16n8k16), fp32 accumulate.
// (Harness PTX stage targets compute_103 — no tcgen05.)
//
// out = swish_poly(X @ W1^T + b1) @ W2^T + b2
// X:[8192,1024] W1:[4096,1024] W2:[1024,4096], fp32 row-major, K contiguous.
//
// R13 == R12 with the compile fix (__half2_as_uint -> explicit pack struct).
// fp16 operands have the SAME 10 mantissa bits as tf32 (fp32 accumulate),
// but legacy HMMA fp16 is 2x the tf32 rate and operands are half the bytes
// -> smem crossbar requirement halves; tensor becomes the sole limiter.
// Pipeline skeleton from R11: 3-stage cp.async, wait_group 1, single
// barrier/iter, cross-barrier fragment prefetch, A JIT single-buffer,
// B double-buffer.

#define BM 128
#define BN 128
#define BKH 64                               // K halves per stage (128 B/row)
#define PADH 8
#define LDSS (BKH + PADH)                    // 72 halves = 144 B row stride
#define A_STAGE_H (BM * LDSS)                // 9216 halves
#define A_STAGE_BYTES (A_STAGE_H * 2)        // 18432
#define STAGE_BYTES (2 * A_STAGE_BYTES)      // 36864
#define STAGES 3
#define NTHREADS 256
#define SMEM_DYN (STAGES * STAGE_BYTES)      // 110592

__device__ __align__(16) __half g_midh[8192UL * 4096UL];
__device__ __align__(16) __half g_Xh  [8192UL * 1024UL];
__device__ __align__(16) __half g_W1h [4096UL * 1024UL];
__device__ __align__(16) __half g_W2h [1024UL * 4096UL];

__device__ __forceinline__ uint32_t stou(const void* p) {
    uint32_t a;
    asm("{ .reg .u64 t; cvta.to.shared.u64 t, %1; cvt.u32.u64 %0, t; }"
        : "=r"(a) : "l"(p));
    return a;
}

__device__ __forceinline__ void cpa16(const __half* smem_dst, const __half* gsrc) {
    uint32_t a = stou(smem_dst);
    asm volatile("cp.async.cg.shared.global [%0], [%1], 16;" :: "r"(a), "l"(gsrc));
}

#define LDSM4(r, addr) \
    asm volatile("ldmatrix.sync.aligned.m8n8.x4.shared.b16 {%0,%1,%2,%3}, [%4];" \
                 : "=r"((r)[0]), "=r"((r)[1]), "=r"((r)[2]), "=r"((r)[3])       \
                 : "r"(addr))

template<bool SWISH, bool HALF_OUT>
__global__ __launch_bounds__(NTHREADS, 2)
void ffn_gemm(const __half* __restrict__ A,   // [M, K] fp16
              const __half* __restrict__ B,   // [N, K] fp16
              const float* __restrict__ bias, // [N] fp32
              void* __restrict__ Cv,          // [M, N] half or float
              int M, int N, int K)
{
    extern __shared__ __align__(16) __half smem[];
    const uint32_t smem_u32 = stou(smem);

    const int tid  = threadIdx.x;
    const int wid  = tid >> 5, lane = tid & 31;
    const int wr   = wid >> 2, wc   = wid & 3;   // 2x4 warp grid -> 64x32 warp tile
    const int lr   = lane >> 2, lc  = lane & 3;
    const int rowBase = blockIdx.y * BM;
    const int colBase = blockIdx.x * BN;
    const int NC = K / BKH;

    // ldmatrix lane addressing (byte offsets within a stage).
    // A frag mi (m16k16): matrices {r0-7,k0-7},{r8-15,k0-7},{r0-7,k8-15},{r8-15,k8-15}
    //   lane t: row += ((t>>3)&1)*8, kbyte += ((t>>4)&1)*16
    // B pair p (n16k16, serves ni=2p,2p+1): {n0-7,k0-7},{n0-7,k8-15},{n8-15,k0-7},{n8-15,k8-15}
    //   lane t: n += ((t>>4)&1)*8, kbyte += ((t>>3)&1)*16
    const int t8  = lane & 7;
    const int tb3 = (lane >> 3) & 1;
    const int tb4 = (lane >> 4) & 1;
    uint32_t a_off[4], b_off[2];
#pragma unroll
    for (int mi = 0; mi < 4; mi++)
        a_off[mi] = (uint32_t)((wr * 64 + mi * 16 + t8 + tb3 * 8) * (LDSS * 2) + tb4 * 16);
#pragma unroll
    for (int p = 0; p < 2; p++)
        b_off[p] = (uint32_t)(A_STAGE_BYTES +
                              (wc * 32 + p * 16 + t8 + tb4 * 8) * (LDSS * 2) + tb3 * 16);

    float acc[4][4][4];
#pragma unroll
    for (int mi = 0; mi < 4; mi++)
#pragma unroll
        for (int ni = 0; ni < 4; ni++)
#pragma unroll
            for (int e = 0; e < 4; e++) acc[mi][ni][e] = 0.0f;

    // Per-thread incremental gmem pointers (advance BKH halves per stage).
    const int ldrow = tid >> 3;
    const int ldq   = (tid & 7) * 8;             // half offset within row
    const __half* aLd = A + (size_t)(rowBase + ldrow) * K + ldq;
    const __half* bLd = B + (size_t)(colBase + ldrow) * K + ldq;

    #define LOAD_STAGE(s, aP, bP) do {                                         \
        __half* sa_ = smem + (s) * (STAGE_BYTES / 2);                          \
        __half* sb_ = sa_ + A_STAGE_H;                                         \
        _Pragma("unroll")                                                      \
        for (int it_ = 0; it_ < 4; it_++)                                      \
            cpa16(sa_ + (ldrow + it_ * 32) * LDSS + ldq,                       \
                  (aP) + (size_t)(it_ * 32) * K);                              \
        _Pragma("unroll")                                                      \
        for (int it_ = 0; it_ < 4; it_++)                                      \
            cpa16(sb_ + (ldrow + it_ * 32) * LDSS + ldq,                       \
                  (bP) + (size_t)(it_ * 32) * K);                              \
    } while (0)

    #define LOADA_ONE(sb_addr, s, mi_, afb) \
        LDSM4((afb)[mi_], (sb_addr) + a_off[mi_] + (s) * 32)

    #define LOADB(sb_addr, s, bfb) do {                                        \
        _Pragma("unroll")                                                      \
        for (int p_ = 0; p_ < 2; p_++)                                         \
            LDSM4((bfb)[p_], (sb_addr) + b_off[p_] + (s) * 32);                \
    } while (0)

    #define MMA_ROW(mi_, afrag, bfb) do {                                      \
        _Pragma("unroll")                                                      \
        for (int ni_ = 0; ni_ < 4; ni_++)                                      \
            asm volatile(                                                      \
                "mma.sync.aligned.m16n8k16.row.col.f32.f16.f16.f32 "           \
                "{%0,%1,%2,%3}, {%4,%5,%6,%7}, {%8,%9}, {%0,%1,%2,%3};"        \
                : "+f"(acc[mi_][ni_][0]), "+f"(acc[mi_][ni_][1]),              \
                  "+f"(acc[mi_][ni_][2]), "+f"(acc[mi_][ni_][3])               \
                : "r"((afrag)[0]), "r"((afrag)[1]),                            \
                  "r"((afrag)[2]), "r"((afrag)[3]),                            \
                  "r"((bfb)[ni_ >> 1][(ni_ & 1) * 2]),                         \
                  "r"((bfb)[ni_ >> 1][(ni_ & 1) * 2 + 1]));                    \
    } while (0)

    // Prologue: load stages 0 and 1; wait stage 0, barrier, prefetch s0 frags.
    LOAD_STAGE(0, aLd, bLd); aLd += BKH; bLd += BKH;
    asm volatile("cp.async.commit_group;" ::: "memory");
    LOAD_STAGE(1, aLd, bLd); aLd += BKH; bLd += BKH;
    asm volatile("cp.async.commit_group;" ::: "memory");
    asm volatile("cp.async.wait_group 1;" ::: "memory");
    __syncthreads();

    uint32_t af[4][4];            // A: single-buffered, JIT reloaded
    uint32_t bf[2][2][4];         // B: double-buffered
#pragma unroll
    for (int mi = 0; mi < 4; mi++) LOADA_ONE(smem_u32, 0, mi, af);
    LOADB(smem_u32, 0, bf[0]);

    for (int c = 0; c < NC; c++) {
        const uint32_t sbase = smem_u32 + (c % STAGES) * STAGE_BYTES;
        const bool haveNextStage = (c + 2 < NC);

#pragma unroll
        for (int s = 0; s < 4; s++) {             // 4 k16 steps (BKH=64)
            const int cur = s & 1;
            if (s < 3) LOADB(sbase, s + 1, bf[cur ^ 1]);
#pragma unroll
            for (int mi = 0; mi < 4; mi++) {
                MMA_ROW(mi, af[mi], bf[cur]);
                if (s < 3) LOADA_ONE(sbase, s + 1, mi, af);
            }
            if (s == 0) {
                if (haveNextStage) {
                    LOAD_STAGE((c + 2) % STAGES, aLd, bLd);
                    aLd += BKH; bLd += BKH;
                }
                asm volatile("cp.async.commit_group;" ::: "memory");
            }
        }

        asm volatile("cp.async.wait_group 1;" ::: "memory");
        __syncthreads();
        if (c + 1 < NC) {
            const uint32_t snext = smem_u32 + ((c + 1) % STAGES) * STAGE_BYTES;
#pragma unroll
            for (int mi = 0; mi < 4; mi++) LOADA_ONE(snext, 0, mi, af);
            LOADB(snext, 0, bf[0]);
        }
    }

    // Epilogue: bias + optional poly-swish; store half (mid) or float (out).
#pragma unroll
    for (int ni = 0; ni < 4; ni++) {
        const int col = colBase + wc * 32 + ni * 8 + 2 * lc;
        const float bv0 = __ldg(bias + col);
        const float bv1 = __ldg(bias + col + 1);
#pragma unroll
        for (int mi = 0; mi < 4; mi++) {
#pragma unroll
            for (int h = 0; h < 2; h++) {
                const int row = rowBase + wr * 64 + mi * 16 + lr + h * 8;
                float v0 = acc[mi][ni][2 * h]     + bv0;
                float v1 = acc[mi][ni][2 * h + 1] + bv1;
                if (SWISH) {
                    float s0 = fmaf(-0.0208f * v0 * v0, v0, fmaf(0.25f, v0, 0.5f));
                    float s1 = fmaf(-0.0208f * v1 * v1, v1, fmaf(0.25f, v1, 0.5f));
                    v0 *= s0; v1 *= s1;
                }
                if (HALF_OUT) {
                    __half* C = (__half*)Cv;
                    *reinterpret_cast<__half2*>(C + (size_t)row * N + col) =
                        __floats2half2_rn(v0, v1);
                } else {
                    float* C = (float*)Cv;
                    *reinterpret_cast<float2*>(C + (size_t)row * N + col) =
                        make_float2(v0, v1);
                }
            }
        }
    }
}

// -------------------- fused fp32 -> fp16 pre-pass ---------------------------
// Index space over groups of 8 floats (reads 2x float4, writes 16B of halves).

struct __align__(16) Half8 { __half2 a, b, c, d; };

__global__ void to_half_fused(const float4* __restrict__ x,  __half* __restrict__ xh,  int n1,
                              const float4* __restrict__ w1, __half* __restrict__ w1h, int n2,
                              const float4* __restrict__ w2, __half* __restrict__ w2h, int n3)
{
    int i = blockIdx.x * blockDim.x + threadIdx.x;   // group of 8 floats
    const float4* src; __half* dst; int j;
    if (i < n1)                { src = x;  dst = xh;  j = i; }
    else if (i < n1 + n2)      { src = w1; dst = w1h; j = i - n1; }
    else if (i < n1 + n2 + n3) { src = w2; dst = w2h; j = i - n1 - n2; }
    else return;
    float4 v0 = src[j * 2];
    float4 v1 = src[j * 2 + 1];
    Half8 pack;
    pack.a = __floats2half2_rn(v0.x, v0.y);
    pack.b = __floats2half2_rn(v0.z, v0.w);
    pack.c = __floats2half2_rn(v1.x, v1.y);
    pack.d = __floats2half2_rn(v1.z, v1.w);
    *reinterpret_cast<Half8*>(dst + (size_t)j * 8) = pack;
}

// ------------------------------- launch -------------------------------------

extern "C" void kernel_launch(void* const* d_in, const int* in_sizes, int n_in,
                              void* d_out, int out_size)
{
    const float* X  = (const float*)d_in[0]; // [M, D]
    const float* W1 = (const float*)d_in[1]; // [F, D]
    const float* b1 = (const float*)d_in[2]; // [F]
    const float* W2 = (const float*)d_in[3]; // [D, F]
    const float* b2 = (const float*)d_in[4]; // [D]
    float* out = (float*)d_out;              // [M, D]

    const int F = in_sizes[2];               // 4096
    const int D = in_sizes[4];               // 1024
    const int M = in_sizes[0] / D;           // 8192

    __half *midh, *Xh, *W1h, *W2h;
    cudaGetSymbolAddress((void**)&midh, g_midh);
    cudaGetSymbolAddress((void**)&Xh,   g_Xh);
    cudaGetSymbolAddress((void**)&W1h,  g_W1h);
    cudaGetSymbolAddress((void**)&W2h,  g_W2h);

    cudaFuncSetAttribute(ffn_gemm<true,  true >,
                         cudaFuncAttributeMaxDynamicSharedMemorySize, SMEM_DYN);
    cudaFuncSetAttribute(ffn_gemm<false, false>,
                         cudaFuncAttributeMaxDynamicSharedMemorySize, SMEM_DYN);

    // Convert inputs to fp16 (RN). One launch; index = groups of 8 floats.
    const int n1 = (M * D) / 8, n2 = (F * D) / 8, n3 = (D * F) / 8;
    const int ntot = n1 + n2 + n3;
    to_half_fused<<<(ntot + 255) / 256, 256>>>(
        (const float4*)X,  Xh,  n1,
        (const float4*)W1, W1h, n2,
        (const float4*)W2, W2h, n3);

    // GEMM1: midh = half(swish(X @ W1^T + b1))   [M, F], K = D
    {
        dim3 grid(F / BN, M / BM);
        ffn_gemm<true, true><<<grid, NTHREADS, SMEM_DYN>>>(Xh, W1h, b1, midh, M, F, D);
    }
    // GEMM2: out = midh @ W2^T + b2               [M, D], K = F
    {
        dim3 grid(D / BN, M / BM);
        ffn_gemm<false, false><<<grid, NTHREADS, SMEM_DYN>>>(midh, W2h, b2, out, M, D, F);
    }
}